// round 10
// baseline (speedup 1.0000x reference)
#include <cuda_runtime.h>

// PZCell biquad: one 128-thread block per row (T=2048), thread = 16-step chunk.
// y[t] = b0 x[t] + b1 x[t-1] + b2 x[t-2] - a1 y[t-1] - a2 y[t-2]   (den == 1)
// Per warp: cp.async own coalesced 2KB slice -> Phase A zero-state recurrence
// in swizzled SMEM -> warp scan (T=M^16, A=M^(16*lane) built in-loop) ->
// block combine: warp exits -> affine carry C_w (M^512) -> true entries ->
// fused-correction coalesced store (W = M^(4*(tid&3))).

namespace {
constexpr int T_LEN   = 2048;
constexpr int B_ROWS  = 4096;
constexpr int THREADS = 128;
}

// chunk c (16 floats), granule g (0..3): XOR swizzle, conflict-free for the
// warp-slice load/store pattern and the per-thread chunk pattern.
__device__ __forceinline__ int swz(int c, int g) {
    return c * 16 + ((g ^ ((c >> 1) & 3)) << 2);
}

__device__ __forceinline__ void cp_async16(float* dst, const float* src) {
    unsigned s = (unsigned)__cvta_generic_to_shared(dst);
    asm volatile("cp.async.cg.shared.global [%0], [%1], 16;" :: "r"(s), "l"(src));
}
__device__ __forceinline__ void cp_commit() { asm volatile("cp.async.commit_group;"); }
__device__ __forceinline__ void cp_wait0()  { asm volatile("cp.async.wait_group 0;" ::: "memory"); }

struct Coef { float a1, a2, A2, Bc, b0, b1, b2; };
struct Mat  { float m00, m01, m10, m11; };

__device__ __forceinline__ Mat mat_sq(const Mat& a) {
    Mat r;
    r.m00 = a.m00*a.m00 + a.m01*a.m10;  r.m01 = a.m00*a.m01 + a.m01*a.m11;
    r.m10 = a.m10*a.m00 + a.m11*a.m10;  r.m11 = a.m10*a.m01 + a.m11*a.m11;
    return r;
}
__device__ __forceinline__ Mat mat_mul(const Mat& a, const Mat& b) {
    Mat r;
    r.m00 = a.m00*b.m00 + a.m01*b.m10;  r.m01 = a.m00*b.m01 + a.m01*b.m11;
    r.m10 = a.m10*b.m00 + a.m11*b.m10;  r.m11 = a.m10*b.m01 + a.m11*b.m11;
    return r;
}

// 4 recurrence steps; updates (x1,x2,p,q), returns z quad
__device__ __forceinline__ float4 step4(const Coef& c, float4 xv,
                                        float& x1, float& x2, float& p, float& q)
{
    float u0 = fmaf(c.b0, xv.x, fmaf(c.b1, x1,   c.b2 * x2));
    float u1 = fmaf(c.b0, xv.y, fmaf(c.b1, xv.x, c.b2 * x1));
    float u2 = fmaf(c.b0, xv.z, fmaf(c.b1, xv.y, c.b2 * xv.x));
    float u3 = fmaf(c.b0, xv.w, fmaf(c.b1, xv.z, c.b2 * xv.y));
    x2 = xv.z; x1 = xv.w;
    float w1 = fmaf(-c.a1, u0, u1);
    float w3 = fmaf(-c.a1, u2, u3);
    float yA = fmaf(-c.a1, p,  fmaf(-c.a2, q,  u0));
    float yB = fmaf( c.A2, p,  fmaf( c.Bc, q,  w1));
    float yC = fmaf(-c.a1, yB, fmaf(-c.a2, yA, u2));
    float yD = fmaf( c.A2, yB, fmaf( c.Bc, yA, w3));
    p = yD; q = yC;
    return make_float4(yA, yB, yC, yD);
}

__global__ void __launch_bounds__(THREADS, 8)
pzA_kernel(const float* __restrict__ x, const float* __restrict__ gain_ri,
           const float* __restrict__ poles_ri, const float* __restrict__ zeros_ri,
           float* __restrict__ out)
{
    __shared__ float tile[2048];   // row data (in-place x -> z)
    __shared__ float ent[256];     // per-chunk true entry (Ex,Ey) x 128
    __shared__ float wex[8];       // per-warp zero-entry exit (dx,dy) x 4

    const int tid  = threadIdx.x;
    const int lane = tid & 31;
    const int w    = tid >> 5;
    const int row  = blockIdx.x;
    const float* xr = x   + (long)row * T_LEN;
    float*       yr = out + (long)row * T_LEN;

    // warp-edge boundary via gmem (independent of SMEM residency)
    float gx1 = 0.f, gx2 = 0.f;
    if (lane == 0 && w > 0) { gx1 = xr[w * 512 - 1]; gx2 = xr[w * 512 - 2]; }

    // ---- cp.async: warp w loads its own 2KB slice, coalesced ----
    #pragma unroll
    for (int i = 0; i < 4; ++i) {
        int ch = w * 32 + i * 8 + (lane >> 2);
        cp_async16(tile + swz(ch, lane & 3), xr + w * 512 + i * 128 + lane * 4);
    }
    cp_commit();

    // ---- coefficients + matrix powers (overlap with loads) ----
    Coef c;
    {
        const float gr = gain_ri[0],  gi = gain_ri[1];
        const float pr0 = poles_ri[0], pi0 = poles_ri[1];
        const float pr1 = poles_ri[2], pi1 = poles_ri[3];
        const float zr0 = zeros_ri[0], zi0 = zeros_ri[1];
        const float zr1 = zeros_ri[2], zi1 = zeros_ri[3];
        c.a1 = -(pr0 + pr1);
        c.a2 = pr0 * pr1 - pi0 * pi1;
        const float zc1r = -(zr0 + zr1), zc1i = -(zi0 + zi1);
        const float zc2r = zr0 * zr1 - zi0 * zi1;
        const float zc2i = zr0 * zi1 + zi0 * zr1;
        c.b0 = gr;
        c.b1 = gr * zc1r - gi * zc1i;
        c.b2 = gr * zc2r - gi * zc2i;
        c.A2 = c.a1 * c.a1 - c.a2;
        c.Bc = c.a1 * c.a2;
    }
    Mat M1  = { -c.a1, -c.a2, 1.f, 0.f };
    Mat M4  = mat_sq(mat_sq(M1));
    Mat M8  = mat_sq(M4);
    Mat M16 = mat_sq(M8);

    cp_wait0();
    __syncwarp();    // all lanes' copies of this warp's slice complete & visible

    // ---- boundary x[-1], x[-2] of this thread's chunk ----
    float x1, x2;
    if (lane > 0) {
        int cc = tid - 1;   // same warp slice
        int off = cc * 16 + ((3 ^ ((cc >> 1) & 3)) << 2);
        x1 = tile[off + 3];
        x2 = tile[off + 2];
    } else {
        x1 = gx1; x2 = gx2;   // tid==0 -> zeros
    }
    __syncwarp();    // boundary reads complete before Phase A overwrites tails

    // ---- Phase A: 16-step zero-entry recurrence in place ----
    float p = 0.f, q = 0.f;
    #pragma unroll
    for (int g = 0; g < 4; ++g) {
        float4 xv = *reinterpret_cast<float4*>(tile + swz(tid, g));
        float4 zv = step4(c, xv, x1, x2, p, q);
        *reinterpret_cast<float4*>(tile + swz(tid, g)) = zv;
    }

    // ---- warp scan (T = M^16), building A = M^(16*lane) in-loop ----
    Mat m = M16;
    Mat A = { 1.f, 0.f, 0.f, 1.f };
    float vx = p, vy = q;
    #pragma unroll
    for (int i = 0; i < 5; ++i) {
        float ox = __shfl_up_sync(0xffffffffu, vx, 1u << i);
        float oy = __shfl_up_sync(0xffffffffu, vy, 1u << i);
        if (lane >= (1 << i)) {
            vx = fmaf(m.m00, ox, fmaf(m.m01, oy, vx));
            vy = fmaf(m.m10, ox, fmaf(m.m11, oy, vy));
        }
        if ((lane >> i) & 1) A = mat_mul(m, A);
        if (i < 4) m = mat_sq(m);
    }
    // m = M^256 now
    float ex = __shfl_up_sync(0xffffffffu, vx, 1);   // zero-seeded exclusive entry
    float ey = __shfl_up_sync(0xffffffffu, vy, 1);
    if (lane == 0) { ex = 0.f; ey = 0.f; }
    if (lane == 31) { wex[2 * w] = vx; wex[2 * w + 1] = vy; }   // warp exit d_w
    Mat M512 = mat_sq(m);

    __syncthreads();

    // ---- cross-warp affine carry: C_w = f_{w-1}(...f_0(0)), f_j(s)=M512*s+d_j ----
    float Cx = 0.f, Cy = 0.f;
    if (w > 0) { Cx = wex[0]; Cy = wex[1]; }
    if (w > 1) {
        float tx = fmaf(M512.m00, Cx, fmaf(M512.m01, Cy, wex[2]));
        float ty = fmaf(M512.m10, Cx, fmaf(M512.m11, Cy, wex[3]));
        Cx = tx; Cy = ty;
    }
    if (w > 2) {
        float tx = fmaf(M512.m00, Cx, fmaf(M512.m01, Cy, wex[4]));
        float ty = fmaf(M512.m10, Cx, fmaf(M512.m11, Cy, wex[5]));
        Cx = tx; Cy = ty;
    }
    // true entry of this thread's chunk: E = A*C + e
    float Ex = fmaf(A.m00, Cx, fmaf(A.m01, Cy, ex));
    float Ey = fmaf(A.m10, Cx, fmaf(A.m11, Cy, ey));
    ent[2 * tid]     = Ex;
    ent[2 * tid + 1] = Ey;

    __syncthreads();

    // ---- coalesced store with fused homogeneous correction ----
    // iteration it: thread stores float4 at pos = it*512 + tid*4;
    // chunk ch = it*32 + (tid>>2), granule = tid&3, W = M^(4*(tid&3)).
    Mat W = { 1.f, 0.f, 0.f, 1.f };
    if (tid & 1) W = M4;
    if (tid & 2) W = mat_mul(M8, W);
    #pragma unroll
    for (int it = 0; it < 4; ++it) {
        int ch = it * 32 + (tid >> 2);
        float sx = ent[2 * ch];
        float sy = ent[2 * ch + 1];
        float s1 = fmaf(W.m00, sx, W.m01 * sy);
        float s2 = fmaf(W.m10, sx, W.m11 * sy);
        float hA = fmaf(-c.a1, s1, -c.a2 * s2);
        float hB = fmaf( c.A2, s1,  c.Bc * s2);
        float hC = fmaf(-c.a1, hB, -c.a2 * hA);
        float hD = fmaf( c.A2, hB,  c.Bc * hA);
        float4 zv = *reinterpret_cast<float4*>(tile + swz(ch, tid & 3));
        zv.x += hA; zv.y += hB; zv.z += hC; zv.w += hD;
        *reinterpret_cast<float4*>(yr + it * 512 + tid * 4) = zv;
    }
}

extern "C" void kernel_launch(void* const* d_in, const int* in_sizes, int n_in,
                              void* d_out, int out_size) {
    (void)in_sizes; (void)n_in; (void)out_size;
    const float* x        = (const float*)d_in[0];
    const float* gain_ri  = (const float*)d_in[1];
    const float* poles_ri = (const float*)d_in[2];
    const float* zeros_ri = (const float*)d_in[3];
    float* out = (float*)d_out;

    pzA_kernel<<<B_ROWS, THREADS>>>(x, gain_ri, poles_ri, zeros_ri, out);
}